// round 1
// baseline (speedup 1.0000x reference)
#include <cuda_runtime.h>
#include <cstdint>

// Problem dims (fixed by the reference)
#define BB   16
#define TT   512
#define HH   512
#define BT   (BB*TT)        // 8192
#define NH   8
#define DH   64             // head dim
#define NBH  (BB*NH)        // 128 batched attention mats

// ---------------------------------------------------------------------------
// Scratch (static device globals — no allocation)
// ---------------------------------------------------------------------------
__device__ float g_Q [(size_t)BT*HH];
__device__ float g_K [(size_t)BT*HH];
__device__ float g_V [(size_t)BT*HH];
__device__ float g_O [(size_t)BT*HH];
__device__ float g_X [(size_t)BT*HH];
__device__ float g_WX[(size_t)BT*HH];
__device__ float g_S [(size_t)NBH*TT*TT];     // 134 MB attention scores
__device__ float g_psum[(size_t)256*HH];
__device__ float g_psq [(size_t)256*HH];
__device__ float g_sum [HH];
__device__ float g_sq  [HH];

// ---------------------------------------------------------------------------
// Accurate expf that is immune to --use_fast_math (softmax must track the
// fp32 reference closely; spike flips are precision-sensitive).
// ---------------------------------------------------------------------------
__device__ __forceinline__ float exp_acc(float x) {
    x = fmaxf(x, -87.0f);
    float z = x * 1.44269504088896341f;
    float n = rintf(z);
    float f = fmaf(n, -0.693145751953125f, x);       // ln2 hi
    f = fmaf(n, -1.428606765330187e-06f, f);         // ln2 lo
    float p = 1.9841269841e-4f;
    p = fmaf(p, f, 1.3888888889e-3f);
    p = fmaf(p, f, 8.3333333333e-3f);
    p = fmaf(p, f, 4.1666666667e-2f);
    p = fmaf(p, f, 1.6666666667e-1f);
    p = fmaf(p, f, 0.5f);
    p = fmaf(p, f, 1.0f);
    p = fmaf(p, f, 1.0f);
    int ni = (int)n;
    float sc = __int_as_float((ni + 127) << 23);
    return p * sc;
}

// ---------------------------------------------------------------------------
// Generic tiled fp32 GEMM: C[z] = alpha * A[z] * op(B[z]) (+ R[z])
//   A: M x K row-major (lda), B: NN -> K x N (ldb), NT -> N x K (ldb)
//   Batched via blockIdx.z with two-level (batch, head) offsets.
//   BM=BN=64, BK=16, 256 threads, 4x4 per thread. All dims multiples of tile.
// ---------------------------------------------------------------------------
template<bool TRANSB, bool RESID>
__global__ __launch_bounds__(256)
void gemm_kernel(const float* __restrict__ A, const float* __restrict__ Bm,
                 float* __restrict__ C, const float* __restrict__ R,
                 int M, int N, int K, int lda, int ldb, int ldc, float alpha,
                 int heads, long sAb, long sAh, long sBb, long sBh,
                 long sCb, long sCh)
{
    const int z = blockIdx.z;
    const int zb = z / heads, zh = z % heads;
    A  += (size_t)zb * sAb + (size_t)zh * sAh;
    Bm += (size_t)zb * sBb + (size_t)zh * sBh;
    const size_t coff = (size_t)zb * sCb + (size_t)zh * sCh;
    C += coff;
    if (RESID) R += coff;

    const int tid = threadIdx.x;
    const int tx  = tid & 15;        // 0..15 -> 4 N cols each
    const int ty  = tid >> 4;        // 0..15 -> 4 M rows each
    const int m0  = blockIdx.y * 64;
    const int n0  = blockIdx.x * 64;

    __shared__ __align__(16) float As[16][68];
    __shared__ __align__(16) float Bs[16][68];

    float acc[4][4] = {};

    const int lr  = tid >> 2;        // 0..63 (row of tile)
    const int lkq = tid & 3;         // 0..3  (float4 index along K)

    for (int k0 = 0; k0 < K; k0 += 16) {
        // ---- load A tile (64 x 16), transpose into As[k][m]
        {
            float4 av = *reinterpret_cast<const float4*>(
                &A[(size_t)(m0 + lr) * lda + k0 + lkq * 4]);
            As[lkq*4 + 0][lr] = av.x;
            As[lkq*4 + 1][lr] = av.y;
            As[lkq*4 + 2][lr] = av.z;
            As[lkq*4 + 3][lr] = av.w;
        }
        // ---- load B tile into Bs[k][n]
        if (TRANSB) {
            float4 bv = *reinterpret_cast<const float4*>(
                &Bm[(size_t)(n0 + lr) * ldb + k0 + lkq * 4]);
            Bs[lkq*4 + 0][lr] = bv.x;
            Bs[lkq*4 + 1][lr] = bv.y;
            Bs[lkq*4 + 2][lr] = bv.z;
            Bs[lkq*4 + 3][lr] = bv.w;
        } else {
            #pragma unroll
            for (int i = 0; i < 4; i++) {
                int idx = tid + i * 256;
                int kk = idx >> 6, nn = idx & 63;
                Bs[kk][nn] = Bm[(size_t)(k0 + kk) * ldb + n0 + nn];
            }
        }
        __syncthreads();

        #pragma unroll
        for (int kk = 0; kk < 16; kk++) {
            float4 av = *reinterpret_cast<const float4*>(&As[kk][ty << 2]);
            float4 bv = *reinterpret_cast<const float4*>(&Bs[kk][tx << 2]);
            float aa[4] = {av.x, av.y, av.z, av.w};
            float bb[4] = {bv.x, bv.y, bv.z, bv.w};
            #pragma unroll
            for (int i = 0; i < 4; i++)
                #pragma unroll
                for (int j = 0; j < 4; j++)
                    acc[i][j] = fmaf(aa[i], bb[j], acc[i][j]);
        }
        __syncthreads();
    }

    #pragma unroll
    for (int i = 0; i < 4; i++) {
        size_t off = (size_t)(m0 + (ty << 2) + i) * ldc + n0 + (tx << 2);
        float4 o;
        o.x = acc[i][0] * alpha;
        o.y = acc[i][1] * alpha;
        o.z = acc[i][2] * alpha;
        o.w = acc[i][3] * alpha;
        if (RESID) {
            float4 rv = *reinterpret_cast<const float4*>(&R[off]);
            o.x += rv.x; o.y += rv.y; o.z += rv.z; o.w += rv.w;
        }
        *reinterpret_cast<float4*>(&C[off]) = o;
    }
}

// ---------------------------------------------------------------------------
// Row softmax over last dim (512). One block (128 thr) per row, in place.
// ---------------------------------------------------------------------------
__global__ __launch_bounds__(128)
void softmax_kernel(float* __restrict__ S)
{
    __shared__ float red[8];
    const int t = threadIdx.x;
    float* p = S + (size_t)blockIdx.x * 512;

    float x0 = p[t], x1 = p[t + 128], x2 = p[t + 256], x3 = p[t + 384];
    float m = fmaxf(fmaxf(x0, x1), fmaxf(x2, x3));
    #pragma unroll
    for (int o = 16; o; o >>= 1)
        m = fmaxf(m, __shfl_xor_sync(0xffffffffu, m, o));
    if ((t & 31) == 0) red[t >> 5] = m;
    __syncthreads();
    m = fmaxf(fmaxf(red[0], red[1]), fmaxf(red[2], red[3]));

    float e0 = exp_acc(x0 - m), e1 = exp_acc(x1 - m);
    float e2 = exp_acc(x2 - m), e3 = exp_acc(x3 - m);
    float s = (e0 + e1) + (e2 + e3);
    #pragma unroll
    for (int o = 16; o; o >>= 1)
        s += __shfl_xor_sync(0xffffffffu, s, o);
    if ((t & 31) == 0) red[4 + (t >> 5)] = s;
    __syncthreads();
    s = (red[4] + red[5]) + (red[6] + red[7]);

    float inv = 1.0f / s;
    p[t]       = e0 * inv;
    p[t + 128] = e1 * inv;
    p[t + 256] = e2 * inv;
    p[t + 384] = e3 * inv;
}

// ---------------------------------------------------------------------------
// BatchNorm stats, deterministic 2-stage (no float atomics => graph-replay
// deterministic, spike threshold must not wobble between runs).
// ---------------------------------------------------------------------------
__global__ __launch_bounds__(256)
void bn_stage1(const float* __restrict__ WX, float* __restrict__ psum,
               float* __restrict__ psq)
{
    const int blk = blockIdx.x;       // 256 blocks, 32 rows each
    const int t   = threadIdx.x;      // 256 threads -> 2 channels each
    const float* base = WX + (size_t)blk * 32 * HH;
    float s0 = 0.f, s1 = 0.f, q0 = 0.f, q1 = 0.f;
    for (int r = 0; r < 32; r++) {
        float a0 = base[(size_t)r * HH + t];
        float a1 = base[(size_t)r * HH + t + 256];
        s0 += a0; q0 = fmaf(a0, a0, q0);
        s1 += a1; q1 = fmaf(a1, a1, q1);
    }
    psum[(size_t)blk * HH + t]       = s0;
    psum[(size_t)blk * HH + t + 256] = s1;
    psq [(size_t)blk * HH + t]       = q0;
    psq [(size_t)blk * HH + t + 256] = q1;
}

__global__ __launch_bounds__(512)
void bn_stage2(const float* __restrict__ psum, const float* __restrict__ psq,
               float* __restrict__ sum, float* __restrict__ sq)
{
    const int h = threadIdx.x;        // 512
    float s = 0.f, q = 0.f;
    for (int i = 0; i < 256; i++) {
        s += psum[(size_t)i * HH + h];
        q += psq [(size_t)i * HH + h];
    }
    sum[h] = s;
    sq[h]  = q;
}

// ---------------------------------------------------------------------------
// Fused BN + LIF scan. One thread per (b, h); coalesced column reads; 8-deep
// load batching to expose MLP against the 512-step sequential dependency.
// ---------------------------------------------------------------------------
__global__ __launch_bounds__(256)
void lif_kernel(const float* __restrict__ WX,
                const float* __restrict__ sum, const float* __restrict__ sq,
                const float* __restrict__ gamma, const float* __restrict__ beta,
                float* __restrict__ out)
{
    const int g = blockIdx.x * blockDim.x + threadIdx.x;   // 0..8191
    const int b = g >> 9;
    const int h = g & 511;

    const float inv_n = 1.0f / (float)BT;
    float mu  = sum[h] * inv_n;
    float var = fmaf(-mu, mu, sq[h] * inv_n);
    float scale = gamma[h] * __frsqrt_rn(var + 1e-5f);   // correctly-rounded rsqrt
    float shift = fmaf(-mu, scale, beta[h]);

    const float* wp = WX  + (size_t)b * TT * HH + h;
    float*       op = out + (size_t)b * TT * HH + h;

    float u = 0.0f;
    for (int t = 0; t < TT; t += 8) {
        float w[8];
        #pragma unroll
        for (int j = 0; j < 8; j++)
            w[j] = wp[(size_t)(t + j) * HH];
        #pragma unroll
        for (int j = 0; j < 8; j++) {
            u = fmaf(0.5f, u, fmaf(w[j], scale, shift));
            float s = (u > 1.0f) ? 1.0f : 0.0f;
            op[(size_t)(t + j) * HH] = s;
            u = (1.0f - s) * u;
        }
    }
}

// ---------------------------------------------------------------------------
// Launch
// ---------------------------------------------------------------------------
extern "C" void kernel_launch(void* const* d_in, const int* in_sizes, int n_in,
                              void* d_out, int out_size)
{
    const float* v     = (const float*)d_in[0];
    const float* a     = (const float*)d_in[1];
    const float* Wq    = (const float*)d_in[2];
    const float* Wk    = (const float*)d_in[3];
    const float* Wv    = (const float*)d_in[4];
    const float* Wo    = (const float*)d_in[5];
    const float* W     = (const float*)d_in[6];
    const float* gamma = (const float*)d_in[7];
    const float* beta  = (const float*)d_in[8];
    float* out = (float*)d_out;

    float *Q, *K, *V, *O, *X, *WX, *S, *PS, *PQ, *SM, *SQ;
    cudaGetSymbolAddress((void**)&Q,  g_Q);
    cudaGetSymbolAddress((void**)&K,  g_K);
    cudaGetSymbolAddress((void**)&V,  g_V);
    cudaGetSymbolAddress((void**)&O,  g_O);
    cudaGetSymbolAddress((void**)&X,  g_X);
    cudaGetSymbolAddress((void**)&WX, g_WX);
    cudaGetSymbolAddress((void**)&S,  g_S);
    cudaGetSymbolAddress((void**)&PS, g_psum);
    cudaGetSymbolAddress((void**)&PQ, g_psq);
    cudaGetSymbolAddress((void**)&SM, g_sum);
    cudaGetSymbolAddress((void**)&SQ, g_sq);

    const long TH = (long)TT * HH;     // 262144
    const long T2 = (long)TT * TT;     // 262144

    // 1-3) Projections: Q = v@Wq, K = a@Wk, V = a@Wv   [8192x512 @ 512x512]
    gemm_kernel<false,false><<<dim3(8,128,1), 256>>>(v, Wq, Q, nullptr,
        BT, HH, HH, HH, HH, HH, 1.0f, 1, 0,0,0,0,0,0);
    gemm_kernel<false,false><<<dim3(8,128,1), 256>>>(a, Wk, K, nullptr,
        BT, HH, HH, HH, HH, HH, 1.0f, 1, 0,0,0,0,0,0);
    gemm_kernel<false,false><<<dim3(8,128,1), 256>>>(a, Wv, V, nullptr,
        BT, HH, HH, HH, HH, HH, 1.0f, 1, 0,0,0,0,0,0);

    // 4) Scores S[bh] = (1/8) * Q_h @ K_h^T   [512x512, K=64], 128 batches
    gemm_kernel<true,false><<<dim3(8,8,NBH), 256>>>(Q, K, S, nullptr,
        TT, TT, DH, HH, HH, TT, 0.125f,
        NH, TH, DH, TH, DH, (long)NH*T2, T2);

    // 5) Row softmax (in place): 128*512 rows of 512
    softmax_kernel<<<NBH*TT, 128>>>(S);

    // 6) O[bh] = P @ V_h   [512x64, K=512], 128 batches
    gemm_kernel<false,false><<<dim3(1,8,NBH), 256>>>(S, V, O, nullptr,
        TT, DH, TT, TT, HH, HH, 1.0f,
        NH, (long)NH*T2, T2, TH, DH, TH, DH);

    // 7) X = O @ Wo + a
    gemm_kernel<false,true><<<dim3(8,128,1), 256>>>(O, Wo, X, a,
        BT, HH, HH, HH, HH, HH, 1.0f, 1, 0,0,0,0,0,0);

    // 8) WX = X @ W
    gemm_kernel<false,false><<<dim3(8,128,1), 256>>>(X, W, WX, nullptr,
        BT, HH, HH, HH, HH, HH, 1.0f, 1, 0,0,0,0,0,0);

    // 9-10) Deterministic BN stats
    bn_stage1<<<256, 256>>>(WX, PS, PQ);
    bn_stage2<<<1, 512>>>(PS, PQ, SM, SQ);

    // 11) Fused BN + LIF scan -> spikes
    lif_kernel<<<BT/ (256*TT/TT) / 1 ? 32 : 32, 256>>>(WX, SM, SQ, gamma, beta, out);
}

// round 2
// speedup vs baseline: 1.2261x; 1.2261x over previous
#include <cuda_runtime.h>
#include <cstdint>

// Problem dims (fixed by the reference)
#define BB   16
#define TT   512
#define HH   512
#define BT   (BB*TT)        // 8192
#define NH   8
#define DH   64             // head dim
#define NBH  (BB*NH)        // 128 batched attention mats

typedef unsigned long long ull;

// ---------------------------------------------------------------------------
// Scratch (static device globals — no allocation)
// ---------------------------------------------------------------------------
__device__ float g_Q [(size_t)BT*HH];
__device__ float g_K [(size_t)BT*HH];
__device__ float g_V [(size_t)BT*HH];
__device__ float g_O [(size_t)BT*HH];
__device__ float g_X [(size_t)BT*HH];
__device__ float g_WX[(size_t)BT*HH];
__device__ float g_S [(size_t)NBH*TT*TT];     // 134 MB attention scores
__device__ float g_psum[(size_t)256*HH];
__device__ float g_psq [(size_t)256*HH];
__device__ float g_sum [HH];
__device__ float g_sq  [HH];

// ---------------------------------------------------------------------------
// f32x2 packed math (sm_103a FFMA2 — PTX-only, ptxas never emits from C++)
// ---------------------------------------------------------------------------
__device__ __forceinline__ ull pack2(float x, float y) {
    ull r; asm("mov.b64 %0, {%1, %2};" : "=l"(r) : "f"(x), "f"(y)); return r;
}
__device__ __forceinline__ ull ffma2(ull a, ull b, ull c) {
    ull d; asm("fma.rn.f32x2 %0, %1, %2, %3;" : "=l"(d) : "l"(a), "l"(b), "l"(c));
    return d;
}
__device__ __forceinline__ void unpack2(ull v, float& x, float& y) {
    asm("mov.b64 {%0, %1}, %2;" : "=f"(x), "=f"(y) : "l"(v));
}

// ---------------------------------------------------------------------------
// Accurate expf, immune to --use_fast_math.
// ---------------------------------------------------------------------------
__device__ __forceinline__ float exp_acc(float x) {
    x = fmaxf(x, -87.0f);
    float z = x * 1.44269504088896341f;
    float n = rintf(z);
    float f = fmaf(n, -0.693145751953125f, x);
    f = fmaf(n, -1.428606765330187e-06f, f);
    float p = 1.9841269841e-4f;
    p = fmaf(p, f, 1.3888888889e-3f);
    p = fmaf(p, f, 8.3333333333e-3f);
    p = fmaf(p, f, 4.1666666667e-2f);
    p = fmaf(p, f, 1.6666666667e-1f);
    p = fmaf(p, f, 0.5f);
    p = fmaf(p, f, 1.0f);
    p = fmaf(p, f, 1.0f);
    int ni = (int)n;
    float sc = __int_as_float((ni + 127) << 23);
    return p * sc;
}

// ---------------------------------------------------------------------------
// fp32 GEMM with f32x2 packed accumulation.
//   C[z] = alpha * A[z] * op(B[z]) (+ R[z])
//   BM=128, BK=16, 256 threads, TM=8, TN (8 or 4) per thread.
//   Register-prefetch single-buffer pipeline; 2 CTAs/SM.
// ---------------------------------------------------------------------------
template<int BN, int TN, bool TRANSB, bool RESID>
__global__ __launch_bounds__(256, 2)
void gemm2(const float* __restrict__ A, const float* __restrict__ Bm,
           float* __restrict__ C, const float* __restrict__ R,
           int M, int N, int K, int lda, int ldb, int ldc, float alpha,
           int heads, long sAb, long sAh, long sBb, long sBh,
           long sCb, long sCh)
{
    constexpr int BM = 128, BK = 16;
    constexpr int NPAIR = TN / 2;        // acc pairs per row
    constexpr int BQ = BN / 4;           // float4 slots per B row (NN layout)

    __shared__ __align__(16) float As[BK][BM + 4];
    __shared__ __align__(16) float Bs[BK][BN + 4];

    const int z = blockIdx.z;
    const int zb = z / heads, zh = z % heads;
    A  += (size_t)zb * sAb + (size_t)zh * sAh;
    Bm += (size_t)zb * sBb + (size_t)zh * sBh;
    const size_t coff = (size_t)zb * sCb + (size_t)zh * sCh;

    const int tid = threadIdx.x;
    const int tx  = tid & 15;
    const int ty  = tid >> 4;
    const int m0  = blockIdx.y * BM;
    const int n0  = blockIdx.x * BN;

    // loader indices
    const int ar = tid >> 2;             // 0..63
    const int aq = tid & 3;              // float4 index along K
    const int bk = tid / BQ;             // NN: k-row within chunk
    const int bq = tid % BQ;             // NN: float4 slot along N
    constexpr int BIT = (BK * BQ + 255) / 256;   // iters to cover B tile (NN)

    float4 pa[2], pb[2];

    // ---- prefetch helpers
    auto loadA = [&](int k0) {
        #pragma unroll
        for (int it = 0; it < 2; it++)
            pa[it] = *reinterpret_cast<const float4*>(
                &A[(size_t)(m0 + ar + it * 64) * lda + k0 + aq * 4]);
    };
    auto loadB = [&](int k0) {
        if (TRANSB) {
            #pragma unroll
            for (int it = 0; it < 2; it++)
                pb[it] = *reinterpret_cast<const float4*>(
                    &Bm[(size_t)(n0 + ar + it * 64) * ldb + k0 + aq * 4]);
        } else {
            #pragma unroll
            for (int it = 0; it < BIT; it++) {
                int idx = tid + it * 256;
                int kk = idx / BQ, nn = idx % BQ;
                pb[it] = *reinterpret_cast<const float4*>(
                    &Bm[(size_t)(k0 + kk) * ldb + n0 + nn * 4]);
            }
        }
    };
    auto storeTiles = [&]() {
        #pragma unroll
        for (int it = 0; it < 2; it++) {
            As[aq*4 + 0][ar + it*64] = pa[it].x;
            As[aq*4 + 1][ar + it*64] = pa[it].y;
            As[aq*4 + 2][ar + it*64] = pa[it].z;
            As[aq*4 + 3][ar + it*64] = pa[it].w;
        }
        if (TRANSB) {
            #pragma unroll
            for (int it = 0; it < 2; it++) {
                Bs[aq*4 + 0][ar + it*64] = pb[it].x;
                Bs[aq*4 + 1][ar + it*64] = pb[it].y;
                Bs[aq*4 + 2][ar + it*64] = pb[it].z;
                Bs[aq*4 + 3][ar + it*64] = pb[it].w;
            }
        } else {
            #pragma unroll
            for (int it = 0; it < BIT; it++) {
                int idx = tid + it * 256;
                int kk = idx / BQ, nn = idx % BQ;
                *reinterpret_cast<float4*>(&Bs[kk][nn * 4]) = pb[it];
            }
        }
    };

    ull acc[8][NPAIR];
    #pragma unroll
    for (int i = 0; i < 8; i++)
        #pragma unroll
        for (int j = 0; j < NPAIR; j++) acc[i][j] = 0ull;

    loadA(0); loadB(0);

    for (int k0 = 0; k0 < K; k0 += BK) {
        storeTiles();
        __syncthreads();
        int kn = k0 + BK;
        if (kn < K) { loadA(kn); loadB(kn); }

        #pragma unroll
        for (int kk = 0; kk < BK; kk++) {
            float4 av0 = *reinterpret_cast<const float4*>(&As[kk][ty * 4]);
            float4 av1 = *reinterpret_cast<const float4*>(&As[kk][ty * 4 + 64]);
            float a8[8] = {av0.x, av0.y, av0.z, av0.w,
                           av1.x, av1.y, av1.z, av1.w};
            ull aa[8];
            #pragma unroll
            for (int i = 0; i < 8; i++) aa[i] = pack2(a8[i], a8[i]);

            ull bp[NPAIR];
            {
                ulonglong2 b0 = *reinterpret_cast<const ulonglong2*>(&Bs[kk][tx * 4]);
                bp[0] = b0.x; bp[1] = b0.y;
                if (TN == 8) {
                    ulonglong2 b1 = *reinterpret_cast<const ulonglong2*>(&Bs[kk][tx * 4 + 64]);
                    bp[2] = b1.x; bp[3] = b1.y;
                }
            }
            #pragma unroll
            for (int i = 0; i < 8; i++)
                #pragma unroll
                for (int j = 0; j < NPAIR; j++)
                    acc[i][j] = ffma2(aa[i], bp[j], acc[i][j]);
        }
        __syncthreads();
    }

    // ---- epilogue
    C += coff;
    if (RESID) R += coff;
    #pragma unroll
    for (int i = 0; i < 8; i++) {
        int row = m0 + ty * 4 + (i & 3) + ((i >> 2) * 64);
        #pragma unroll
        for (int g = 0; g < TN / 4; g++) {
            size_t off = (size_t)row * ldc + n0 + tx * 4 + g * 64;
            float4 o;
            unpack2(acc[i][2*g + 0], o.x, o.y);
            unpack2(acc[i][2*g + 1], o.z, o.w);
            o.x *= alpha; o.y *= alpha; o.z *= alpha; o.w *= alpha;
            if (RESID) {
                float4 rv = *reinterpret_cast<const float4*>(&R[off]);
                o.x += rv.x; o.y += rv.y; o.z += rv.z; o.w += rv.w;
            }
            *reinterpret_cast<float4*>(&C[off]) = o;
        }
    }
}

// ---------------------------------------------------------------------------
// Row softmax over last dim (512). One block (128 thr) per row, in place.
// ---------------------------------------------------------------------------
__global__ __launch_bounds__(128)
void softmax_kernel(float* __restrict__ S)
{
    __shared__ float red[8];
    const int t = threadIdx.x;
    float* p = S + (size_t)blockIdx.x * 512;

    float x0 = p[t], x1 = p[t + 128], x2 = p[t + 256], x3 = p[t + 384];
    float m = fmaxf(fmaxf(x0, x1), fmaxf(x2, x3));
    #pragma unroll
    for (int o = 16; o; o >>= 1)
        m = fmaxf(m, __shfl_xor_sync(0xffffffffu, m, o));
    if ((t & 31) == 0) red[t >> 5] = m;
    __syncthreads();
    m = fmaxf(fmaxf(red[0], red[1]), fmaxf(red[2], red[3]));

    float e0 = exp_acc(x0 - m), e1 = exp_acc(x1 - m);
    float e2 = exp_acc(x2 - m), e3 = exp_acc(x3 - m);
    float s = (e0 + e1) + (e2 + e3);
    #pragma unroll
    for (int o = 16; o; o >>= 1)
        s += __shfl_xor_sync(0xffffffffu, s, o);
    if ((t & 31) == 0) red[4 + (t >> 5)] = s;
    __syncthreads();
    s = (red[4] + red[5]) + (red[6] + red[7]);

    float inv = 1.0f / s;
    p[t]       = e0 * inv;
    p[t + 128] = e1 * inv;
    p[t + 256] = e2 * inv;
    p[t + 384] = e3 * inv;
}

// ---------------------------------------------------------------------------
// Deterministic 2-stage BatchNorm stats (graph-replay deterministic).
// ---------------------------------------------------------------------------
__global__ __launch_bounds__(256)
void bn_stage1(const float* __restrict__ WX, float* __restrict__ psum,
               float* __restrict__ psq)
{
    const int blk = blockIdx.x;
    const int t   = threadIdx.x;
    const float* base = WX + (size_t)blk * 32 * HH;
    float s0 = 0.f, s1 = 0.f, q0 = 0.f, q1 = 0.f;
    for (int r = 0; r < 32; r++) {
        float a0 = base[(size_t)r * HH + t];
        float a1 = base[(size_t)r * HH + t + 256];
        s0 += a0; q0 = fmaf(a0, a0, q0);
        s1 += a1; q1 = fmaf(a1, a1, q1);
    }
    psum[(size_t)blk * HH + t]       = s0;
    psum[(size_t)blk * HH + t + 256] = s1;
    psq [(size_t)blk * HH + t]       = q0;
    psq [(size_t)blk * HH + t + 256] = q1;
}

__global__ __launch_bounds__(512)
void bn_stage2(const float* __restrict__ psum, const float* __restrict__ psq,
               float* __restrict__ sum, float* __restrict__ sq)
{
    const int h = threadIdx.x;
    float s = 0.f, q = 0.f;
    for (int i = 0; i < 256; i++) {
        s += psum[(size_t)i * HH + h];
        q += psq [(size_t)i * HH + h];
    }
    sum[h] = s;
    sq[h]  = q;
}

// ---------------------------------------------------------------------------
// Fused BN + LIF scan. One thread per (b, h); 8-deep load batching.
// ---------------------------------------------------------------------------
__global__ __launch_bounds__(256)
void lif_kernel(const float* __restrict__ WX,
                const float* __restrict__ sum, const float* __restrict__ sq,
                const float* __restrict__ gamma, const float* __restrict__ beta,
                float* __restrict__ out)
{
    const int g = blockIdx.x * blockDim.x + threadIdx.x;
    const int b = g >> 9;
    const int h = g & 511;

    const float inv_n = 1.0f / (float)BT;
    float mu  = sum[h] * inv_n;
    float var = fmaf(-mu, mu, sq[h] * inv_n);
    float scale = gamma[h] * __frsqrt_rn(var + 1e-5f);
    float shift = fmaf(-mu, scale, beta[h]);

    const float* wp = WX  + (size_t)b * TT * HH + h;
    float*       op = out + (size_t)b * TT * HH + h;

    float u = 0.0f;
    for (int t = 0; t < TT; t += 8) {
        float w[8];
        #pragma unroll
        for (int j = 0; j < 8; j++)
            w[j] = wp[(size_t)(t + j) * HH];
        #pragma unroll
        for (int j = 0; j < 8; j++) {
            u = fmaf(0.5f, u, fmaf(w[j], scale, shift));
            float s = (u > 1.0f) ? 1.0f : 0.0f;
            op[(size_t)(t + j) * HH] = s;
            u = (1.0f - s) * u;
        }
    }
}

// ---------------------------------------------------------------------------
// Launch
// ---------------------------------------------------------------------------
extern "C" void kernel_launch(void* const* d_in, const int* in_sizes, int n_in,
                              void* d_out, int out_size)
{
    const float* v     = (const float*)d_in[0];
    const float* a     = (const float*)d_in[1];
    const float* Wq    = (const float*)d_in[2];
    const float* Wk    = (const float*)d_in[3];
    const float* Wv    = (const float*)d_in[4];
    const float* Wo    = (const float*)d_in[5];
    const float* W     = (const float*)d_in[6];
    const float* gamma = (const float*)d_in[7];
    const float* beta  = (const float*)d_in[8];
    float* out = (float*)d_out;

    float *Q, *K, *V, *O, *X, *WX, *S, *PS, *PQ, *SM, *SQ;
    cudaGetSymbolAddress((void**)&Q,  g_Q);
    cudaGetSymbolAddress((void**)&K,  g_K);
    cudaGetSymbolAddress((void**)&V,  g_V);
    cudaGetSymbolAddress((void**)&O,  g_O);
    cudaGetSymbolAddress((void**)&X,  g_X);
    cudaGetSymbolAddress((void**)&WX, g_WX);
    cudaGetSymbolAddress((void**)&S,  g_S);
    cudaGetSymbolAddress((void**)&PS, g_psum);
    cudaGetSymbolAddress((void**)&PQ, g_psq);
    cudaGetSymbolAddress((void**)&SM, g_sum);
    cudaGetSymbolAddress((void**)&SQ, g_sq);

    const long TH = (long)TT * HH;     // 262144
    const long T2 = (long)TT * TT;     // 262144

    // 1-3) Projections: Q = v@Wq, K = a@Wk, V = a@Wv   [8192x512 @ 512x512]
    gemm2<128,8,false,false><<<dim3(4,64,1), 256>>>(v, Wq, Q, nullptr,
        BT, HH, HH, HH, HH, HH, 1.0f, 1, 0,0,0,0,0,0);
    gemm2<128,8,false,false><<<dim3(4,64,1), 256>>>(a, Wk, K, nullptr,
        BT, HH, HH, HH, HH, HH, 1.0f, 1, 0,0,0,0,0,0);
    gemm2<128,8,false,false><<<dim3(4,64,1), 256>>>(a, Wv, V, nullptr,
        BT, HH, HH, HH, HH, HH, 1.0f, 1, 0,0,0,0,0,0);

    // 4) Scores S[bh] = (1/8) * Q_h @ K_h^T   [512x512, K=64], 128 batches
    gemm2<128,8,true,false><<<dim3(4,4,NBH), 256>>>(Q, K, S, nullptr,
        TT, TT, DH, HH, HH, TT, 0.125f,
        NH, TH, DH, TH, DH, (long)NH*T2, T2);

    // 5) Row softmax (in place): 128*512 rows of 512
    softmax_kernel<<<NBH*TT, 128>>>(S);

    // 6) O[bh] = P @ V_h   [512x64, K=512], 128 batches
    gemm2<64,4,false,false><<<dim3(1,4,NBH), 256>>>(S, V, O, nullptr,
        TT, DH, TT, TT, HH, HH, 1.0f,
        NH, (long)NH*T2, T2, TH, DH, TH, DH);

    // 7) X = O @ Wo + a
    gemm2<128,8,false,true><<<dim3(4,64,1), 256>>>(O, Wo, X, a,
        BT, HH, HH, HH, HH, HH, 1.0f, 1, 0,0,0,0,0,0);

    // 8) WX = X @ W
    gemm2<128,8,false,false><<<dim3(4,64,1), 256>>>(X, W, WX, nullptr,
        BT, HH, HH, HH, HH, HH, 1.0f, 1, 0,0,0,0,0,0);

    // 9-10) Deterministic BN stats
    bn_stage1<<<256, 256>>>(WX, PS, PQ);
    bn_stage2<<<1, 512>>>(PS, PQ, SM, SQ);

    // 11) Fused BN + LIF scan -> spikes
    lif_kernel<<<32, 256>>>(WX, SM, SQ, gamma, beta, out);
}